// round 9
// baseline (speedup 1.0000x reference)
#include <cuda_runtime.h>
#include <math.h>

#define Bq   8
#define Sq   1024
#define Eq   256
#define Hq   256
#define H2q  512
#define Cq   64

// ---------------- static device scratch ----------------
__device__ __align__(16) float g_x    [Bq*Sq*Eq];
__device__ __align__(16) float g_xgf  [Bq*Sq*3*Hq];
__device__ __align__(16) float g_xgb  [Bq*Sq*3*Hq];
__device__ __align__(16) float g_bigru[Bq*Sq*H2q];
__device__ __align__(16) float g_xgu  [Bq*Sq*3*H2q];
__device__ __align__(16) float g_U    [Bq*Sq*H2q];
__device__ __align__(16) float g_energ[Bq*Sq*Sq];
__device__ __align__(16) float g_ctx  [Bq*Sq*H2q];
__device__ __align__(16) float g_cfcfc[Bq*Sq*H2q];
__device__ __align__(16) float g_cfc  [Bq*Sq*H2q];
__device__ __align__(16) float g_htfc [Bq*Sq*H2q];
__device__ __align__(16) float g_ft   [Bq*Sq*H2q];

__device__ __align__(16) float g_hf[2][Hq*8];
__device__ __align__(16) float g_hb[2][Hq*8];
__device__ __align__(16) float g_hu[2][H2q*8];

// distributed per-CTA step flags (zeroed by zero_flags_k each launch)
__device__ __align__(16) unsigned g_flagF [64];
__device__ __align__(16) unsigned g_flagBk[64];
__device__ __align__(16) unsigned g_flagU [128];

// ---------------- fast activations ----------------
__device__ __forceinline__ float fsig(float x) {
    return __fdividef(1.f, 1.f + __expf(-x));
}
__device__ __forceinline__ float ftanh(float x) {
    return 1.f - __fdividef(2.f, __expf(2.f * x) + 1.f);
}

// L2-scoped poll: .cg reads the L2 coherence point WITHOUT invalidating the
// line (unlike .cv, which forces a DRAM refetch + line invalidation and
// caused an inter-CTA ping-pong storm in R8). asm volatile blocks hoisting.
__device__ __forceinline__ unsigned ldcg_u32(const unsigned* p) {
    unsigned v;
    asm volatile("ld.global.cg.u32 %0, [%1];" : "=r"(v) : "l"(p));
    return v;
}

__global__ void zero_flags_k()
{
    const int i = threadIdx.x;
    if (i < 64) { g_flagF[i] = 0u; g_flagBk[i] = 0u; }
    if (i < 128) g_flagU[i] = 0u;
}

// ---------------- persistent GRU scan worker (flag-sync) ----------------
// 4 outputs j per CTA. 192 thr: tid = q*12 + (j*3+gate), q in [0,16).
// Recurrent weights register-resident; h staged to smem [k][b] each step.
// Sync: each CTA stores step+1 into its own flag slot; pollers read all slots.
template<int K>
__device__ __forceinline__ void scan_worker(
    int j0,
    const float* __restrict__ xg,     // [B*S][3K] (includes input bias)
    const float* __restrict__ wh,     // [3K][K]
    const float* __restrict__ bh,     // [3K]
    float* hA, float* hB,             // ping-pong [K*8] ([k][b])
    float* __restrict__ outbase, int out_off,
    int reverse_time,
    unsigned* flags, int mycta, int ncta,
    float* u0base, int u0_off,
    int shift_out)
{
    constexpr int ROWS = 12;          // 4 j * 3 gates
    constexpr int Q    = 16;          // k-slices
    constexpr int QS   = K / Q;
    const int tid = threadIdx.x;
    const int q   = tid / ROWS;
    const int row = tid % ROWS;
    const int gg  = row % 3;
    const int jg  = j0 + row / 3;

    float wreg[QS];
    {
        const float* wrow = wh + (size_t)(gg * K + jg) * K + q * QS;
#pragma unroll
        for (int i = 0; i < QS; i++) wreg[i] = wrow[i];
    }

    __shared__ float4 h4[K * 2];
    __shared__ float  part[8 * 193];  // stride 193: bank-conflict-free reduce

    // every CTA zeroes the full initial h (same values -> benign overlap)
    for (int i = tid; i < K * 8; i += 192) { __stcg(&hA[i], 0.f); }
    __syncthreads();   // intra-CTA visibility of our own zeroes

    float bhr = 0.f, bhz = 0.f, bhn = 0.f;
    int fb = 0, fjg = 0, fj = 0;
    if (tid < 32) {
        fb  = tid & 7;
        fj  = tid >> 3;               // 0..3
        fjg = j0 + fj;
        bhr = bh[0 * K + fjg];
        bhz = bh[1 * K + fjg];
        bhn = bh[2 * K + fjg];
    }

    float* hsrc = hA;
    float* hdst = hB;
    for (int s = 0; s < Sq; s++) {
        const int t = reverse_time ? (Sq - 1 - s) : s;

        // prefetch this step's xg early (off the critical tail)
        float xgr = 0.f, xgz = 0.f, xgn = 0.f;
        if (tid < 32) {
            const float* xr = xg + ((size_t)fb * Sq + t) * (3 * K);
            xgr = __ldg(xr + fjg);
            xgz = __ldg(xr + K + fjg);
            xgn = __ldg(xr + 2 * K + fjg);
        }

        // stage h (L2 -> smem, bypass L1)
        for (int i = tid; i < K * 2; i += 192)
            h4[i] = __ldcg(((const float4*)hsrc) + i);
        __syncthreads();

        float acc[8];
#pragma unroll
        for (int b = 0; b < 8; b++) acc[b] = 0.f;
        const int kb = q * QS;
#pragma unroll
        for (int i = 0; i < QS; i++) {
            const float  w  = wreg[i];
            const float4 lo = h4[(kb + i) * 2];
            const float4 hi = h4[(kb + i) * 2 + 1];
            acc[0] += w * lo.x; acc[1] += w * lo.y;
            acc[2] += w * lo.z; acc[3] += w * lo.w;
            acc[4] += w * hi.x; acc[5] += w * hi.y;
            acc[6] += w * hi.z; acc[7] += w * hi.w;
        }
#pragma unroll
        for (int b = 0; b < 8; b++) part[b * 193 + q * ROWS + row] = acc[b];
        __syncthreads();

        if (tid < 32) {
            float sr = 0.f, sz = 0.f, sn = 0.f;
#pragma unroll
            for (int qq = 0; qq < Q; qq++) {
                const float* p = &part[fb * 193 + qq * ROWS + fj * 3];
                sr += p[0]; sz += p[1]; sn += p[2];
            }
            const float hold = ((const float*)h4)[fjg * 8 + fb];

            const float r    = fsig(xgr + sr + bhr);
            const float z    = fsig(xgz + sz + bhz);
            const float nn   = ftanh(xgn + r * (sn + bhn));
            const float hnew = (1.f - z) * nn + z * hold;

            __stcg(&hdst[fjg * 8 + fb], hnew);
            const int to = shift_out ? (t + 1) : t;
            if (to < Sq)
                outbase[((size_t)fb * Sq + to) * H2q + out_off + fjg] = hnew;
            if (s == Sq - 1 && u0base)
                u0base[((size_t)fb * Sq) * H2q + u0_off + fjg] = hnew;
            __threadfence();               // release (producer lanes only)
            __syncwarp();
            if (tid == 0)
                __stcg(&flags[mycta], (unsigned)(s + 1));   // announce
        }

        // wait: every flag must reach s+1 (parallel, contention-free, L2 polls)
        if (tid < ncta) {
            const unsigned want = (unsigned)(s + 1);
            unsigned spin = 0;
            while (ldcg_u32(&flags[tid]) < want) {
                if (++spin > 8192u) {
                    __nanosleep(64);
                    if (spin > (1u << 19)) break;   // hang-proofing (~33ms cap)
                }
            }
            __threadfence();               // acquire
        }
        __syncthreads();
        float* tmp = hsrc; hsrc = hdst; hdst = tmp;
    }
}

// fwd = CTAs [0,64), bwd = CTAs [64,128); independent flag groups.
__global__ void __launch_bounds__(192, 1)
scan_fb(const float* xgf, const float* xgb,
        const float* whf, const float* bhf,
        const float* whb, const float* bhb)
{
    const int  cta = blockIdx.x;
    const bool isb = cta >= 64;
    scan_worker<Hq>((isb ? cta - 64 : cta) * 4,
                    isb ? xgb : xgf,
                    isb ? whb : whf,
                    isb ? bhb : bhf,
                    isb ? g_hb[0] : g_hf[0],
                    isb ? g_hb[1] : g_hf[1],
                    g_bigru, isb ? Hq : 0,
                    isb ? 1 : 0,
                    isb ? g_flagBk : g_flagF,
                    isb ? cta - 64 : cta, 64,
                    g_U, isb ? 0 : Hq,   // hidden_cat = [hT_b | hT_f]
                    0);
}

__global__ void __launch_bounds__(192, 1)
scan_uni(const float* xgu, const float* whu, const float* bhu)
{
    scan_worker<H2q>(blockIdx.x * 4, xgu, whu, bhu,
                     g_hu[0], g_hu[1],
                     g_U, 0,
                     0,
                     g_flagU, blockIdx.x, 128,
                     nullptr, 0,
                     1);                 // U[:, t+1] = uni_out[:, t]
}

// ---------------- GEMM: C = A @ W^T + bias (double-buffered, occ 2) ----------------
__global__ void __launch_bounds__(256, 2)
gemm_abt(const float* __restrict__ A, const float* __restrict__ W,
         const float* __restrict__ bias, float* __restrict__ C,
         int M, int N, int K,
         long long sA, long long sW, long long sC)
{
    A += (size_t)blockIdx.z * sA;
    W += (size_t)blockIdx.z * sW;
    C += (size_t)blockIdx.z * sC;

    __shared__ float As[2][8][132];
    __shared__ float Ws[2][8][132];

    const int tid = threadIdx.x;
    const int tx = tid % 16, ty = tid / 16;
    const int m0 = blockIdx.y * 128, n0 = blockIdx.x * 128;
    const int r = tid >> 1, cq = tid & 1;

    const float* Aptr = A + (size_t)(m0 + r) * K + cq * 4;
    const bool   wok  = (n0 + r) < N;
    const float* Wptr = W + (size_t)(n0 + r) * K + cq * 4;

    float acc[8][8];
#pragma unroll
    for (int i = 0; i < 8; i++)
#pragma unroll
        for (int jj = 0; jj < 8; jj++) acc[i][jj] = 0.f;

    float4 a4 = *(const float4*)(Aptr);
    float4 w4 = wok ? *(const float4*)(Wptr) : make_float4(0.f,0.f,0.f,0.f);
    As[0][cq * 4 + 0][r] = a4.x; As[0][cq * 4 + 1][r] = a4.y;
    As[0][cq * 4 + 2][r] = a4.z; As[0][cq * 4 + 3][r] = a4.w;
    Ws[0][cq * 4 + 0][r] = w4.x; Ws[0][cq * 4 + 1][r] = w4.y;
    Ws[0][cq * 4 + 2][r] = w4.z; Ws[0][cq * 4 + 3][r] = w4.w;
    __syncthreads();

    int p = 0;
    for (int k0 = 0; k0 < K; k0 += 8) {
        const bool more = (k0 + 8 < K);
        if (more) {
            a4 = *(const float4*)(Aptr + k0 + 8);
            w4 = wok ? *(const float4*)(Wptr + k0 + 8) : make_float4(0.f,0.f,0.f,0.f);
        }
#pragma unroll
        for (int k = 0; k < 8; k++) {
            float mreg[8], nreg[8];
            *(float4*)&mreg[0] = *(const float4*)&As[p][k][ty * 8];
            *(float4*)&mreg[4] = *(const float4*)&As[p][k][ty * 8 + 4];
            *(float4*)&nreg[0] = *(const float4*)&Ws[p][k][tx * 8];
            *(float4*)&nreg[4] = *(const float4*)&Ws[p][k][tx * 8 + 4];
#pragma unroll
            for (int i = 0; i < 8; i++)
#pragma unroll
                for (int jj = 0; jj < 8; jj++)
                    acc[i][jj] += mreg[i] * nreg[jj];
        }
        if (more) {
            const int pn = p ^ 1;
            As[pn][cq * 4 + 0][r] = a4.x; As[pn][cq * 4 + 1][r] = a4.y;
            As[pn][cq * 4 + 2][r] = a4.z; As[pn][cq * 4 + 3][r] = a4.w;
            Ws[pn][cq * 4 + 0][r] = w4.x; Ws[pn][cq * 4 + 1][r] = w4.y;
            Ws[pn][cq * 4 + 2][r] = w4.z; Ws[pn][cq * 4 + 3][r] = w4.w;
            __syncthreads();
            p = pn;
        }
    }

    float breg[8];
#pragma unroll
    for (int jj = 0; jj < 8; jj++) {
        const int c = n0 + tx * 8 + jj;
        breg[jj] = (bias && c < N) ? bias[c] : 0.f;
    }
    const int c0 = n0 + tx * 8;
#pragma unroll
    for (int i = 0; i < 8; i++) {
        float* crow = C + (size_t)(m0 + ty * 8 + i) * N;
        if (c0 < N) {
            float4 o = { acc[i][0] + breg[0], acc[i][1] + breg[1],
                         acc[i][2] + breg[2], acc[i][3] + breg[3] };
            *(float4*)(crow + c0) = o;
        }
        if (c0 + 4 < N) {
            float4 o = { acc[i][4] + breg[4], acc[i][5] + breg[5],
                         acc[i][6] + breg[6], acc[i][7] + breg[7] };
            *(float4*)(crow + c0 + 4) = o;
        }
    }
}

// ---------------- GEMM: C = A @ B + bias (double-buffered, occ 2) ----------------
__global__ void __launch_bounds__(256, 2)
gemm_ab(const float* __restrict__ A, const float* __restrict__ B,
        const float* __restrict__ bias, float* __restrict__ C,
        int M, int N, int K,
        long long sA, long long sB, long long sC)
{
    A += (size_t)blockIdx.z * sA;
    B += (size_t)blockIdx.z * sB;
    C += (size_t)blockIdx.z * sC;

    __shared__ float As[2][8][132];
    __shared__ float Bs[2][8][132];

    const int tid = threadIdx.x;
    const int tx = tid % 16, ty = tid / 16;
    const int m0 = blockIdx.y * 128, n0 = blockIdx.x * 128;
    const int r = tid >> 1, cq = tid & 1;
    const int kk = tid >> 5, nq = tid & 31;

    const float* Aptr = A + (size_t)(m0 + r) * K + cq * 4;
    const bool   bok  = (n0 + nq * 4) < N;
    const float* Bptr = B + (size_t)kk * N + n0 + nq * 4;

    float acc[8][8];
#pragma unroll
    for (int i = 0; i < 8; i++)
#pragma unroll
        for (int jj = 0; jj < 8; jj++) acc[i][jj] = 0.f;

    float4 a4 = *(const float4*)(Aptr);
    float4 b4 = bok ? *(const float4*)(Bptr) : make_float4(0.f,0.f,0.f,0.f);
    As[0][cq * 4 + 0][r] = a4.x; As[0][cq * 4 + 1][r] = a4.y;
    As[0][cq * 4 + 2][r] = a4.z; As[0][cq * 4 + 3][r] = a4.w;
    *(float4*)&Bs[0][kk][nq * 4] = b4;
    __syncthreads();

    int p = 0;
    for (int k0 = 0; k0 < K; k0 += 8) {
        const bool more = (k0 + 8 < K);
        if (more) {
            a4 = *(const float4*)(Aptr + k0 + 8);
            b4 = bok ? *(const float4*)(Bptr + (size_t)(k0 + 8) * N)
                     : make_float4(0.f,0.f,0.f,0.f);
        }
#pragma unroll
        for (int k = 0; k < 8; k++) {
            float mreg[8], nreg[8];
            *(float4*)&mreg[0] = *(const float4*)&As[p][k][ty * 8];
            *(float4*)&mreg[4] = *(const float4*)&As[p][k][ty * 8 + 4];
            *(float4*)&nreg[0] = *(const float4*)&Bs[p][k][tx * 8];
            *(float4*)&nreg[4] = *(const float4*)&Bs[p][k][tx * 8 + 4];
#pragma unroll
            for (int i = 0; i < 8; i++)
#pragma unroll
                for (int jj = 0; jj < 8; jj++)
                    acc[i][jj] += mreg[i] * nreg[jj];
        }
        if (more) {
            const int pn = p ^ 1;
            As[pn][cq * 4 + 0][r] = a4.x; As[pn][cq * 4 + 1][r] = a4.y;
            As[pn][cq * 4 + 2][r] = a4.z; As[pn][cq * 4 + 3][r] = a4.w;
            *(float4*)&Bs[pn][kk][nq * 4] = b4;
            __syncthreads();
            p = pn;
        }
    }

    float breg[8];
#pragma unroll
    for (int jj = 0; jj < 8; jj++) {
        const int c = n0 + tx * 8 + jj;
        breg[jj] = (bias && c < N) ? bias[c] : 0.f;
    }
    const int c0 = n0 + tx * 8;
#pragma unroll
    for (int i = 0; i < 8; i++) {
        float* crow = C + (size_t)(m0 + ty * 8 + i) * N;
        if (c0 < N) {
            float4 o = { acc[i][0] + breg[0], acc[i][1] + breg[1],
                         acc[i][2] + breg[2], acc[i][3] + breg[3] };
            *(float4*)(crow + c0) = o;
        }
        if (c0 + 4 < N) {
            float4 o = { acc[i][4] + breg[4], acc[i][5] + breg[5],
                         acc[i][6] + breg[6], acc[i][7] + breg[7] };
            *(float4*)(crow + c0 + 4) = o;
        }
    }
}

// ---------------- row softmax over 1024 cols ----------------
__global__ void __launch_bounds__(256, 1)
softmax_rows(float* __restrict__ E)
{
    float4* e4 = (float4*)(E + (size_t)blockIdx.x * Sq);
    const int tid = threadIdx.x;
    float4 v = e4[tid];

    float m = fmaxf(fmaxf(v.x, v.y), fmaxf(v.z, v.w));
#pragma unroll
    for (int o = 16; o > 0; o >>= 1)
        m = fmaxf(m, __shfl_xor_sync(0xffffffffu, m, o));
    __shared__ float wredm[8];
    if ((tid & 31) == 0) wredm[tid >> 5] = m;
    __syncthreads();
    float mm = wredm[0];
#pragma unroll
    for (int i = 1; i < 8; i++) mm = fmaxf(mm, wredm[i]);

    v.x = __expf(v.x - mm); v.y = __expf(v.y - mm);
    v.z = __expf(v.z - mm); v.w = __expf(v.w - mm);
    float s = v.x + v.y + v.z + v.w;
#pragma unroll
    for (int o = 16; o > 0; o >>= 1)
        s += __shfl_xor_sync(0xffffffffu, s, o);
    __shared__ float wreds[8];
    if ((tid & 31) == 0) wreds[tid >> 5] = s;
    __syncthreads();
    float ss = 0.f;
#pragma unroll
    for (int i = 0; i < 8; i++) ss += wreds[i];

    const float inv = __fdividef(1.f, ss);
    v.x *= inv; v.y *= inv; v.z *= inv; v.w *= inv;
    e4[tid] = v;
}

__global__ void embed_k(const int* __restrict__ tok, const float* __restrict__ emb)
{
    const int i = blockIdx.x * blockDim.x + threadIdx.x;
    const int n4 = Bq * Sq * Eq / 4;
    if (i < n4) {
        const int row = i / (Eq / 4);
        const int c   = i % (Eq / 4);
        const int t   = tok[row];
        ((float4*)g_x)[i] = ((const float4*)(emb + (size_t)t * Eq))[c];
    }
}

__global__ void ft_k()
{
    const int i = blockIdx.x * blockDim.x + threadIdx.x;
    const int n4 = Bq * Sq * H2q / 4;
    if (i < n4) {
        const float4 a = ((const float4*)g_cfc)[i];
        const float4 b = ((const float4*)g_cfcfc)[i];
        const float4 c = ((const float4*)g_htfc)[i];
        const float4 d = ((const float4*)g_bigru)[i];
        float4 o;
        o.x = a.x * fsig(b.x + c.x) + d.x;
        o.y = a.y * fsig(b.y + c.y) + d.y;
        o.z = a.z * fsig(b.z + c.z) + d.z;
        o.w = a.w * fsig(b.w + c.w) + d.w;
        ((float4*)g_ft)[i] = o;
    }
}

// ---------------- launch ----------------
static float* sym(const void* s) {
    void* p = nullptr;
    cudaGetSymbolAddress(&p, s);
    return (float*)p;
}

extern "C" void kernel_launch(void* const* d_in, const int* in_sizes, int n_in,
                              void* d_out, int out_size)
{
    (void)in_sizes; (void)n_in; (void)out_size;
    const int*   tok     = (const int*)  d_in[0];
    const float* emb     = (const float*)d_in[2];
    const float* wi_f    = (const float*)d_in[3];
    const float* wh_f    = (const float*)d_in[4];
    const float* bi_f    = (const float*)d_in[5];
    const float* bh_f    = (const float*)d_in[6];
    const float* wi_b    = (const float*)d_in[7];
    const float* wh_b    = (const float*)d_in[8];
    const float* bi_b    = (const float*)d_in[9];
    const float* bh_b    = (const float*)d_in[10];
    const float* uwi     = (const float*)d_in[11];
    const float* uwh     = (const float*)d_in[12];
    const float* ubi     = (const float*)d_in[13];
    const float* ubh     = (const float*)d_in[14];
    const float* w_attn  = (const float*)d_in[15];
    const float* b_attn  = (const float*)d_in[16];
    const float* w_afc   = (const float*)d_in[17];
    const float* b_afc   = (const float*)d_in[18];
    const float* w_ht    = (const float*)d_in[19];
    const float* b_ht    = (const float*)d_in[20];
    const float* w_out   = (const float*)d_in[21];
    const float* b_out   = (const float*)d_in[22];
    float* out = (float*)d_out;

    float* x     = sym(g_x);
    float* xgf   = sym(g_xgf);
    float* xgb   = sym(g_xgb);
    float* bigru = sym(g_bigru);
    float* xgu   = sym(g_xgu);
    float* U     = sym(g_U);
    float* energ = sym(g_energ);
    float* ctx   = sym(g_ctx);
    float* cfc   = sym(g_cfc);
    float* cfcfc = sym(g_cfcfc);
    float* htfc  = sym(g_htfc);
    float* ft    = sym(g_ft);

    const long long sU = (long long)Sq * H2q;
    const long long sE = (long long)Sq * Sq;
    const int M = Bq * Sq;                      // 8192

    zero_flags_k<<<1, 128>>>();
    embed_k<<<(Bq*Sq*Eq/4 + 255)/256, 256>>>(tok, emb);

    gemm_abt<<<dim3(6, 64, 1), 256>>>(x, wi_f, bi_f, xgf, M, 3*Hq, Eq, 0, 0, 0);
    gemm_abt<<<dim3(6, 64, 1), 256>>>(x, wi_b, bi_b, xgb, M, 3*Hq, Eq, 0, 0, 0);

    scan_fb<<<128, 192>>>(xgf, xgb, wh_f, bh_f, wh_b, bh_b);

    gemm_abt<<<dim3(12, 64, 1), 256>>>(bigru, uwi, ubi, xgu, M, 3*H2q, H2q, 0, 0, 0);

    scan_uni<<<128, 192>>>(xgu, uwh, ubh);

    gemm_abt<<<dim3(8, 8, Bq), 256>>>(U, bigru, nullptr, energ,
                                      Sq, Sq, H2q, sU, sU, sE);
    softmax_rows<<<M, 256>>>(energ);
    gemm_ab<<<dim3(4, 8, Bq), 256>>>(energ, bigru, nullptr, ctx,
                                     Sq, H2q, Sq, sE, sU, sU);

    gemm_abt<<<dim3(4, 64, 1), 256>>>(ctx,   w_attn, b_attn, cfc,   M, H2q, H2q, 0, 0, 0);
    gemm_abt<<<dim3(4, 64, 1), 256>>>(cfc,   w_afc,  b_afc,  cfcfc, M, H2q, H2q, 0, 0, 0);
    gemm_abt<<<dim3(4, 64, 1), 256>>>(bigru, w_ht,   b_ht,   htfc,  M, H2q, H2q, 0, 0, 0);

    ft_k<<<(Bq*Sq*H2q/4 + 255)/256, 256>>>();

    gemm_abt<<<dim3(1, 64, 1), 256>>>(ft, w_out, b_out, out, M, Cq, H2q, 0, 0, 0);
}

// round 10
// speedup vs baseline: 1.5488x; 1.5488x over previous
#include <cuda_runtime.h>
#include <math.h>

#define Bq   8
#define Sq   1024
#define Eq   256
#define Hq   256
#define H2q  512
#define Cq   64

// ---------------- static device scratch ----------------
__device__ __align__(16) float g_x    [Bq*Sq*Eq];
__device__ __align__(16) float g_xgf  [Bq*Sq*3*Hq];
__device__ __align__(16) float g_xgb  [Bq*Sq*3*Hq];
__device__ __align__(16) float g_bigru[Bq*Sq*H2q];
__device__ __align__(16) float g_xgu  [Bq*Sq*3*H2q];
__device__ __align__(16) float g_U    [Bq*Sq*H2q];
__device__ __align__(16) float g_energ[Bq*Sq*Sq];
__device__ __align__(16) float g_ctx  [Bq*Sq*H2q];
__device__ __align__(16) float g_cfcfc[Bq*Sq*H2q];
__device__ __align__(16) float g_cfc  [Bq*Sq*H2q];
__device__ __align__(16) float g_htfc [Bq*Sq*H2q];
__device__ __align__(16) float g_ft   [Bq*Sq*H2q];

__device__ __align__(16) float g_hf[2][Hq*8];
__device__ __align__(16) float g_hb[2][Hq*8];
__device__ __align__(16) float g_hu[2][H2q*8];

// hierarchical barrier state: 3 groups (fwd, bwd, uni).
// every counter on its own 128B line to parallelize LTS atomic ALUs.
__device__ int      g_subc[3][8 * 32];   // 8 sub-counters per group
__device__ int      g_rootc[3 * 32];
__device__ unsigned g_genw [3 * 32];

// ---------------- fast activations ----------------
__device__ __forceinline__ float fsig(float x) {
    return __fdividef(1.f, 1.f + __expf(-x));
}
__device__ __forceinline__ float ftanh(float x) {
    return 1.f - __fdividef(2.f, __expf(2.f * x) + 1.f);
}

__global__ void zero_bar_k()
{
    const int i = threadIdx.x;
    if (i < 8 * 32) { g_subc[0][i] = 0; g_subc[1][i] = 0; g_subc[2][i] = 0; }
    if (i < 3 * 32) { g_rootc[i] = 0; g_genw[i] = 0u; }
}

// ---------------- hierarchical grid barrier ----------------
// Arrival: 8 parallel sub-counters -> root counter. Release: single gen word,
// ONE polling thread per CTA (many pollers poison the per-SM L1tex FIFO — R8/R9
// lesson). Completer resets counters before flipping gen (fenced).
__device__ __forceinline__ void grid_barrier_h(int grp, int mycta, int ncta)
{
    __syncthreads();
    if (threadIdx.x == 0) {
        volatile unsigned* gv = &g_genw[grp * 32];
        const unsigned g = *gv;
        const int subn = ncta >> 3;
        if (atomicAdd(&g_subc[grp][(mycta & 7) * 32], 1) == subn - 1) {
            if (atomicAdd(&g_rootc[grp * 32], 1) == 7) {
#pragma unroll
                for (int i = 0; i < 8; i++) g_subc[grp][i * 32] = 0;
                g_rootc[grp * 32] = 0;
                __threadfence();
                *gv = g + 1;
            }
        }
        unsigned spin = 0;
        while (*gv == g) {
            if (++spin > 2048u) {
                __nanosleep(64);
                if (spin > (1u << 19)) break;   // hang-proofing (~33ms cap)
            }
        }
    }
    __syncthreads();
}

// ---------------- persistent GRU scan worker ----------------
// 4 outputs j per CTA. 192 thr: tid = q*12 + (j*3+gate), q in [0,16).
// Recurrent weights register-resident; h staged to smem [k][b] each step.
template<int K>
__device__ __forceinline__ void scan_worker(
    int j0,
    const float* __restrict__ xg,     // [B*S][3K] (includes input bias)
    const float* __restrict__ wh,     // [3K][K]
    const float* __restrict__ bh,     // [3K]
    float* hA, float* hB,             // ping-pong [K*8] ([k][b])
    float* __restrict__ outbase, int out_off,
    int reverse_time,
    int grp, int mycta, int ncta,
    float* u0base, int u0_off,
    int shift_out)
{
    constexpr int ROWS = 12;          // 4 j * 3 gates
    constexpr int Q    = 16;          // k-slices
    constexpr int QS   = K / Q;
    const int tid = threadIdx.x;
    const int q   = tid / ROWS;
    const int row = tid % ROWS;
    const int gg  = row % 3;
    const int jg  = j0 + row / 3;

    float wreg[QS];
    {
        const float* wrow = wh + (size_t)(gg * K + jg) * K + q * QS;
#pragma unroll
        for (int i = 0; i < QS; i++) wreg[i] = wrow[i];
    }

    __shared__ float4 h4[K * 2];
    __shared__ float  part[8 * 193];  // stride 193: bank-conflict-free reduce

    // every CTA zeroes the full initial h (same values -> benign overlap)
    for (int i = tid; i < K * 8; i += 192) { __stcg(&hA[i], 0.f); }
    __syncthreads();

    float bhr = 0.f, bhz = 0.f, bhn = 0.f;
    int fb = 0, fjg = 0, fj = 0;
    if (tid < 32) {
        fb  = tid & 7;
        fj  = tid >> 3;               // 0..3
        fjg = j0 + fj;
        bhr = bh[0 * K + fjg];
        bhz = bh[1 * K + fjg];
        bhn = bh[2 * K + fjg];
    }

    float* hsrc = hA;
    float* hdst = hB;
    for (int s = 0; s < Sq; s++) {
        const int t = reverse_time ? (Sq - 1 - s) : s;

        // prefetch this step's xg early (off the critical tail)
        float xgr = 0.f, xgz = 0.f, xgn = 0.f;
        if (tid < 32) {
            const float* xr = xg + ((size_t)fb * Sq + t) * (3 * K);
            xgr = __ldg(xr + fjg);
            xgz = __ldg(xr + K + fjg);
            xgn = __ldg(xr + 2 * K + fjg);
        }

        // stage h (L2 -> smem, bypass L1)
        for (int i = tid; i < K * 2; i += 192)
            h4[i] = __ldcg(((const float4*)hsrc) + i);
        __syncthreads();

        float acc[8];
#pragma unroll
        for (int b = 0; b < 8; b++) acc[b] = 0.f;
        const int kb = q * QS;
#pragma unroll
        for (int i = 0; i < QS; i++) {
            const float  w  = wreg[i];
            const float4 lo = h4[(kb + i) * 2];
            const float4 hi = h4[(kb + i) * 2 + 1];
            acc[0] += w * lo.x; acc[1] += w * lo.y;
            acc[2] += w * lo.z; acc[3] += w * lo.w;
            acc[4] += w * hi.x; acc[5] += w * hi.y;
            acc[6] += w * hi.z; acc[7] += w * hi.w;
        }
#pragma unroll
        for (int b = 0; b < 8; b++) part[b * 193 + q * ROWS + row] = acc[b];
        __syncthreads();

        if (tid < 32) {
            float sr = 0.f, sz = 0.f, sn = 0.f;
#pragma unroll
            for (int qq = 0; qq < Q; qq++) {
                const float* p = &part[fb * 193 + qq * ROWS + fj * 3];
                sr += p[0]; sz += p[1]; sn += p[2];
            }
            const float hold = ((const float*)h4)[fjg * 8 + fb];

            const float r    = fsig(xgr + sr + bhr);
            const float z    = fsig(xgz + sz + bhz);
            const float nn   = ftanh(xgn + r * (sn + bhn));
            const float hnew = (1.f - z) * nn + z * hold;

            // only hdst must be visible before the announce -> fence now,
            // then issue the output-row stores (consumed by LATER kernels;
            // kernel-end fence covers them).
            __stcg(&hdst[fjg * 8 + fb], hnew);
            __threadfence();               // release for hdst
            const int to = shift_out ? (t + 1) : t;
            if (to < Sq)
                outbase[((size_t)fb * Sq + to) * H2q + out_off + fjg] = hnew;
            if (s == Sq - 1 && u0base)
                u0base[((size_t)fb * Sq) * H2q + u0_off + fjg] = hnew;
        }
        grid_barrier_h(grp, mycta, ncta);
        float* tmp = hsrc; hsrc = hdst; hdst = tmp;
    }
}

// fwd = CTAs [0,64) (grp 0), bwd = CTAs [64,128) (grp 1); run concurrently.
__global__ void __launch_bounds__(192, 1)
scan_fb(const float* xgf, const float* xgb,
        const float* whf, const float* bhf,
        const float* whb, const float* bhb)
{
    const int  cta = blockIdx.x;
    const bool isb = cta >= 64;
    scan_worker<Hq>((isb ? cta - 64 : cta) * 4,
                    isb ? xgb : xgf,
                    isb ? whb : whf,
                    isb ? bhb : bhf,
                    isb ? g_hb[0] : g_hf[0],
                    isb ? g_hb[1] : g_hf[1],
                    g_bigru, isb ? Hq : 0,
                    isb ? 1 : 0,
                    isb ? 1 : 0,
                    isb ? cta - 64 : cta, 64,
                    g_U, isb ? 0 : Hq,   // hidden_cat = [hT_b | hT_f]
                    0);
}

__global__ void __launch_bounds__(192, 1)
scan_uni(const float* xgu, const float* whu, const float* bhu)
{
    scan_worker<H2q>(blockIdx.x * 4, xgu, whu, bhu,
                     g_hu[0], g_hu[1],
                     g_U, 0,
                     0,
                     2, blockIdx.x, 128,
                     nullptr, 0,
                     1);                 // U[:, t+1] = uni_out[:, t]
}

// ---------------- GEMM: C = A @ W^T + bias (double-buffered, occ 2) ----------------
__global__ void __launch_bounds__(256, 2)
gemm_abt(const float* __restrict__ A, const float* __restrict__ W,
         const float* __restrict__ bias, float* __restrict__ C,
         int M, int N, int K,
         long long sA, long long sW, long long sC)
{
    A += (size_t)blockIdx.z * sA;
    W += (size_t)blockIdx.z * sW;
    C += (size_t)blockIdx.z * sC;

    __shared__ float As[2][8][132];
    __shared__ float Ws[2][8][132];

    const int tid = threadIdx.x;
    const int tx = tid % 16, ty = tid / 16;
    const int m0 = blockIdx.y * 128, n0 = blockIdx.x * 128;
    const int r = tid >> 1, cq = tid & 1;

    const float* Aptr = A + (size_t)(m0 + r) * K + cq * 4;
    const bool   wok  = (n0 + r) < N;
    const float* Wptr = W + (size_t)(n0 + r) * K + cq * 4;

    float acc[8][8];
#pragma unroll
    for (int i = 0; i < 8; i++)
#pragma unroll
        for (int jj = 0; jj < 8; jj++) acc[i][jj] = 0.f;

    float4 a4 = *(const float4*)(Aptr);
    float4 w4 = wok ? *(const float4*)(Wptr) : make_float4(0.f,0.f,0.f,0.f);
    As[0][cq * 4 + 0][r] = a4.x; As[0][cq * 4 + 1][r] = a4.y;
    As[0][cq * 4 + 2][r] = a4.z; As[0][cq * 4 + 3][r] = a4.w;
    Ws[0][cq * 4 + 0][r] = w4.x; Ws[0][cq * 4 + 1][r] = w4.y;
    Ws[0][cq * 4 + 2][r] = w4.z; Ws[0][cq * 4 + 3][r] = w4.w;
    __syncthreads();

    int p = 0;
    for (int k0 = 0; k0 < K; k0 += 8) {
        const bool more = (k0 + 8 < K);
        if (more) {
            a4 = *(const float4*)(Aptr + k0 + 8);
            w4 = wok ? *(const float4*)(Wptr + k0 + 8) : make_float4(0.f,0.f,0.f,0.f);
        }
#pragma unroll
        for (int k = 0; k < 8; k++) {
            float mreg[8], nreg[8];
            *(float4*)&mreg[0] = *(const float4*)&As[p][k][ty * 8];
            *(float4*)&mreg[4] = *(const float4*)&As[p][k][ty * 8 + 4];
            *(float4*)&nreg[0] = *(const float4*)&Ws[p][k][tx * 8];
            *(float4*)&nreg[4] = *(const float4*)&Ws[p][k][tx * 8 + 4];
#pragma unroll
            for (int i = 0; i < 8; i++)
#pragma unroll
                for (int jj = 0; jj < 8; jj++)
                    acc[i][jj] += mreg[i] * nreg[jj];
        }
        if (more) {
            const int pn = p ^ 1;
            As[pn][cq * 4 + 0][r] = a4.x; As[pn][cq * 4 + 1][r] = a4.y;
            As[pn][cq * 4 + 2][r] = a4.z; As[pn][cq * 4 + 3][r] = a4.w;
            Ws[pn][cq * 4 + 0][r] = w4.x; Ws[pn][cq * 4 + 1][r] = w4.y;
            Ws[pn][cq * 4 + 2][r] = w4.z; Ws[pn][cq * 4 + 3][r] = w4.w;
            __syncthreads();
            p = pn;
        }
    }

    float breg[8];
#pragma unroll
    for (int jj = 0; jj < 8; jj++) {
        const int c = n0 + tx * 8 + jj;
        breg[jj] = (bias && c < N) ? bias[c] : 0.f;
    }
    const int c0 = n0 + tx * 8;
#pragma unroll
    for (int i = 0; i < 8; i++) {
        float* crow = C + (size_t)(m0 + ty * 8 + i) * N;
        if (c0 < N) {
            float4 o = { acc[i][0] + breg[0], acc[i][1] + breg[1],
                         acc[i][2] + breg[2], acc[i][3] + breg[3] };
            *(float4*)(crow + c0) = o;
        }
        if (c0 + 4 < N) {
            float4 o = { acc[i][4] + breg[4], acc[i][5] + breg[5],
                         acc[i][6] + breg[6], acc[i][7] + breg[7] };
            *(float4*)(crow + c0 + 4) = o;
        }
    }
}

// ---------------- GEMM: C = A @ B + bias (double-buffered, occ 2) ----------------
__global__ void __launch_bounds__(256, 2)
gemm_ab(const float* __restrict__ A, const float* __restrict__ B,
        const float* __restrict__ bias, float* __restrict__ C,
        int M, int N, int K,
        long long sA, long long sB, long long sC)
{
    A += (size_t)blockIdx.z * sA;
    B += (size_t)blockIdx.z * sB;
    C += (size_t)blockIdx.z * sC;

    __shared__ float As[2][8][132];
    __shared__ float Bs[2][8][132];

    const int tid = threadIdx.x;
    const int tx = tid % 16, ty = tid / 16;
    const int m0 = blockIdx.y * 128, n0 = blockIdx.x * 128;
    const int r = tid >> 1, cq = tid & 1;
    const int kk = tid >> 5, nq = tid & 31;

    const float* Aptr = A + (size_t)(m0 + r) * K + cq * 4;
    const bool   bok  = (n0 + nq * 4) < N;
    const float* Bptr = B + (size_t)kk * N + n0 + nq * 4;

    float acc[8][8];
#pragma unroll
    for (int i = 0; i < 8; i++)
#pragma unroll
        for (int jj = 0; jj < 8; jj++) acc[i][jj] = 0.f;

    float4 a4 = *(const float4*)(Aptr);
    float4 b4 = bok ? *(const float4*)(Bptr) : make_float4(0.f,0.f,0.f,0.f);
    As[0][cq * 4 + 0][r] = a4.x; As[0][cq * 4 + 1][r] = a4.y;
    As[0][cq * 4 + 2][r] = a4.z; As[0][cq * 4 + 3][r] = a4.w;
    *(float4*)&Bs[0][kk][nq * 4] = b4;
    __syncthreads();

    int p = 0;
    for (int k0 = 0; k0 < K; k0 += 8) {
        const bool more = (k0 + 8 < K);
        if (more) {
            a4 = *(const float4*)(Aptr + k0 + 8);
            b4 = bok ? *(const float4*)(Bptr + (size_t)(k0 + 8) * N)
                     : make_float4(0.f,0.f,0.f,0.f);
        }
#pragma unroll
        for (int k = 0; k < 8; k++) {
            float mreg[8], nreg[8];
            *(float4*)&mreg[0] = *(const float4*)&As[p][k][ty * 8];
            *(float4*)&mreg[4] = *(const float4*)&As[p][k][ty * 8 + 4];
            *(float4*)&nreg[0] = *(const float4*)&Bs[p][k][tx * 8];
            *(float4*)&nreg[4] = *(const float4*)&Bs[p][k][tx * 8 + 4];
#pragma unroll
            for (int i = 0; i < 8; i++)
#pragma unroll
                for (int jj = 0; jj < 8; jj++)
                    acc[i][jj] += mreg[i] * nreg[jj];
        }
        if (more) {
            const int pn = p ^ 1;
            As[pn][cq * 4 + 0][r] = a4.x; As[pn][cq * 4 + 1][r] = a4.y;
            As[pn][cq * 4 + 2][r] = a4.z; As[pn][cq * 4 + 3][r] = a4.w;
            *(float4*)&Bs[pn][kk][nq * 4] = b4;
            __syncthreads();
            p = pn;
        }
    }

    float breg[8];
#pragma unroll
    for (int jj = 0; jj < 8; jj++) {
        const int c = n0 + tx * 8 + jj;
        breg[jj] = (bias && c < N) ? bias[c] : 0.f;
    }
    const int c0 = n0 + tx * 8;
#pragma unroll
    for (int i = 0; i < 8; i++) {
        float* crow = C + (size_t)(m0 + ty * 8 + i) * N;
        if (c0 < N) {
            float4 o = { acc[i][0] + breg[0], acc[i][1] + breg[1],
                         acc[i][2] + breg[2], acc[i][3] + breg[3] };
            *(float4*)(crow + c0) = o;
        }
        if (c0 + 4 < N) {
            float4 o = { acc[i][4] + breg[4], acc[i][5] + breg[5],
                         acc[i][6] + breg[6], acc[i][7] + breg[7] };
            *(float4*)(crow + c0 + 4) = o;
        }
    }
}

// ---------------- row softmax over 1024 cols ----------------
__global__ void __launch_bounds__(256, 1)
softmax_rows(float* __restrict__ E)
{
    float4* e4 = (float4*)(E + (size_t)blockIdx.x * Sq);
    const int tid = threadIdx.x;
    float4 v = e4[tid];

    float m = fmaxf(fmaxf(v.x, v.y), fmaxf(v.z, v.w));
#pragma unroll
    for (int o = 16; o > 0; o >>= 1)
        m = fmaxf(m, __shfl_xor_sync(0xffffffffu, m, o));
    __shared__ float wredm[8];
    if ((tid & 31) == 0) wredm[tid >> 5] = m;
    __syncthreads();
    float mm = wredm[0];
#pragma unroll
    for (int i = 1; i < 8; i++) mm = fmaxf(mm, wredm[i]);

    v.x = __expf(v.x - mm); v.y = __expf(v.y - mm);
    v.z = __expf(v.z - mm); v.w = __expf(v.w - mm);
    float s = v.x + v.y + v.z + v.w;
#pragma unroll
    for (int o = 16; o > 0; o >>= 1)
        s += __shfl_xor_sync(0xffffffffu, s, o);
    __shared__ float wreds[8];
    if ((tid & 31) == 0) wreds[tid >> 5] = s;
    __syncthreads();
    float ss = 0.f;
#pragma unroll
    for (int i = 0; i < 8; i++) ss += wreds[i];

    const float inv = __fdividef(1.f, ss);
    v.x *= inv; v.y *= inv; v.z *= inv; v.w *= inv;
    e4[tid] = v;
}

__global__ void embed_k(const int* __restrict__ tok, const float* __restrict__ emb)
{
    const int i = blockIdx.x * blockDim.x + threadIdx.x;
    const int n4 = Bq * Sq * Eq / 4;
    if (i < n4) {
        const int row = i / (Eq / 4);
        const int c   = i % (Eq / 4);
        const int t   = tok[row];
        ((float4*)g_x)[i] = ((const float4*)(emb + (size_t)t * Eq))[c];
    }
}

__global__ void ft_k()
{
    const int i = blockIdx.x * blockDim.x + threadIdx.x;
    const int n4 = Bq * Sq * H2q / 4;
    if (i < n4) {
        const float4 a = ((const float4*)g_cfc)[i];
        const float4 b = ((const float4*)g_cfcfc)[i];
        const float4 c = ((const float4*)g_htfc)[i];
        const float4 d = ((const float4*)g_bigru)[i];
        float4 o;
        o.x = a.x * fsig(b.x + c.x) + d.x;
        o.y = a.y * fsig(b.y + c.y) + d.y;
        o.z = a.z * fsig(b.z + c.z) + d.z;
        o.w = a.w * fsig(b.w + c.w) + d.w;
        ((float4*)g_ft)[i] = o;
    }
}

// ---------------- launch ----------------
static float* sym(const void* s) {
    void* p = nullptr;
    cudaGetSymbolAddress(&p, s);
    return (float*)p;
}

extern "C" void kernel_launch(void* const* d_in, const int* in_sizes, int n_in,
                              void* d_out, int out_size)
{
    (void)in_sizes; (void)n_in; (void)out_size;
    const int*   tok     = (const int*)  d_in[0];
    const float* emb     = (const float*)d_in[2];
    const float* wi_f    = (const float*)d_in[3];
    const float* wh_f    = (const float*)d_in[4];
    const float* bi_f    = (const float*)d_in[5];
    const float* bh_f    = (const float*)d_in[6];
    const float* wi_b    = (const float*)d_in[7];
    const float* wh_b    = (const float*)d_in[8];
    const float* bi_b    = (const float*)d_in[9];
    const float* bh_b    = (const float*)d_in[10];
    const float* uwi     = (const float*)d_in[11];
    const float* uwh     = (const float*)d_in[12];
    const float* ubi     = (const float*)d_in[13];
    const float* ubh     = (const float*)d_in[14];
    const float* w_attn  = (const float*)d_in[15];
    const float* b_attn  = (const float*)d_in[16];
    const float* w_afc   = (const float*)d_in[17];
    const float* b_afc   = (const float*)d_in[18];
    const float* w_ht    = (const float*)d_in[19];
    const float* b_ht    = (const float*)d_in[20];
    const float* w_out   = (const float*)d_in[21];
    const float* b_out   = (const float*)d_in[22];
    float* out = (float*)d_out;

    float* x     = sym(g_x);
    float* xgf   = sym(g_xgf);
    float* xgb   = sym(g_xgb);
    float* bigru = sym(g_bigru);
    float* xgu   = sym(g_xgu);
    float* U     = sym(g_U);
    float* energ = sym(g_energ);
    float* ctx   = sym(g_ctx);
    float* cfc   = sym(g_cfc);
    float* cfcfc = sym(g_cfcfc);
    float* htfc  = sym(g_htfc);
    float* ft    = sym(g_ft);

    const long long sU = (long long)Sq * H2q;
    const long long sE = (long long)Sq * Sq;
    const int M = Bq * Sq;                      // 8192

    zero_bar_k<<<1, 256>>>();
    embed_k<<<(Bq*Sq*Eq/4 + 255)/256, 256>>>(tok, emb);

    gemm_abt<<<dim3(6, 64, 1), 256>>>(x, wi_f, bi_f, xgf, M, 3*Hq, Eq, 0, 0, 0);
    gemm_abt<<<dim3(6, 64, 1), 256>>>(x, wi_b, bi_b, xgb, M, 3*Hq, Eq, 0, 0, 0);

    scan_fb<<<128, 192>>>(xgf, xgb, wh_f, bh_f, wh_b, bh_b);

    gemm_abt<<<dim3(12, 64, 1), 256>>>(bigru, uwi, ubi, xgu, M, 3*H2q, H2q, 0, 0, 0);

    scan_uni<<<128, 192>>>(xgu, uwh, ubh);

    gemm_abt<<<dim3(8, 8, Bq), 256>>>(U, bigru, nullptr, energ,
                                      Sq, Sq, H2q, sU, sU, sE);
    softmax_rows<<<M, 256>>>(energ);
    gemm_ab<<<dim3(4, 8, Bq), 256>>>(energ, bigru, nullptr, ctx,
                                     Sq, H2q, Sq, sE, sU, sU);

    gemm_abt<<<dim3(4, 64, 1), 256>>>(ctx,   w_attn, b_attn, cfc,   M, H2q, H2q, 0, 0, 0);
    gemm_abt<<<dim3(4, 64, 1), 256>>>(cfc,   w_afc,  b_afc,  cfcfc, M, H2q, H2q, 0, 0, 0);
    gemm_abt<<<dim3(4, 64, 1), 256>>>(bigru, w_ht,   b_ht,   htfc,  M, H2q, H2q, 0, 0, 0);

    ft_k<<<(Bq*Sq*H2q/4 + 255)/256, 256>>>();

    gemm_abt<<<dim3(1, 64, 1), 256>>>(ft, w_out, b_out, out, M, Cq, H2q, 0, 0, 0);
}

// round 14
// speedup vs baseline: 1.8202x; 1.1752x over previous
#include <cuda_runtime.h>
#include <math.h>

#define Bq   8
#define Sq   1024
#define Eq   256
#define Hq   256
#define H2q  512
#define Cq   64

// ---------------- static device scratch ----------------
__device__ __align__(16) float g_x    [Bq*Sq*Eq];
__device__ __align__(16) float g_xgf  [Bq*Sq*3*Hq];
__device__ __align__(16) float g_xgb  [Bq*Sq*3*Hq];
__device__ __align__(16) float g_bigru[Bq*Sq*H2q];
__device__ __align__(16) float g_xgu  [Bq*Sq*3*H2q];
__device__ __align__(16) float g_U    [Bq*Sq*H2q];
__device__ __align__(16) float g_energ[Bq*Sq*Sq];
__device__ __align__(16) float g_ctx  [Bq*Sq*H2q];
__device__ __align__(16) float g_cfcfc[Bq*Sq*H2q];
__device__ __align__(16) float g_cfc  [Bq*Sq*H2q];
__device__ __align__(16) float g_htfc [Bq*Sq*H2q];
__device__ __align__(16) float g_ft   [Bq*Sq*H2q];

__device__ __align__(16) float g_hf[2][Hq*8];
__device__ __align__(16) float g_hb[2][Hq*8];
__device__ __align__(16) float g_hu[2][H2q*8];

// simple central barrier state (R5 mechanism — empirically best)
__device__ int      g_cnt[4];
__device__ unsigned g_gen[4];

// ---------------- fast activations ----------------
__device__ __forceinline__ float fsig(float x) {
    return __fdividef(1.f, 1.f + __expf(-x));
}
__device__ __forceinline__ float ftanh(float x) {
    return 1.f - __fdividef(2.f, __expf(2.f * x) + 1.f);
}

__global__ void zero_bar_k()
{
    const int i = threadIdx.x;
    if (i < 4) { g_cnt[i] = 0; g_gen[i] = 0u; }
}

// ---------------- central grid barrier (R5 form; 1 atomic, 1 poller/CTA) ----------------
__device__ __forceinline__ void grid_barrier_c(int idx, int bar_n)
{
    __syncthreads();
    if (threadIdx.x == 0) {
        volatile unsigned* gv = &g_gen[idx];
        unsigned g = *gv;
        if (atomicAdd(&g_cnt[idx], 1) == bar_n - 1) {
            g_cnt[idx] = 0;
            __threadfence();
            *gv = g + 1;
        } else {
            unsigned spin = 0;
            while (*gv == g) {
                if (++spin > 2048u) {
                    __nanosleep(64);
                    if (spin > (1u << 19)) break;   // hang-proofing (~33ms)
                }
            }
        }
    }
    __syncthreads();
}

// ---------------- persistent GRU scan worker ----------------
// OUTS outputs j per CTA, NT threads: tid = q*(3*OUTS) + (j*3+gate), q in [0,16).
// Recurrent weights register-resident; h staged to smem [k][b] each step.
// xg for step s+1 prefetched BEFORE the step-s barrier (off the critical chain).
template<int K, int OUTS, int NT>
__device__ __forceinline__ void scan_worker(
    int j0,
    const float* __restrict__ xg,     // [B*S][3K] (includes input bias)
    const float* __restrict__ wh,     // [3K][K]
    const float* __restrict__ bh,     // [3K]
    float* hA, float* hB,             // ping-pong [K*8] ([k][b])
    float* __restrict__ outbase, int out_off,
    int reverse_time,
    int bar_idx, int bar_n,
    float* u0base, int u0_off,
    int shift_out)
{
    constexpr int ROWS = 3 * OUTS;
    constexpr int Q    = NT / ROWS;       // 16
    constexpr int QS   = K / Q;
    constexpr int NP   = OUTS * 8;        // producer threads
    constexpr int PSTR = Q * ROWS + 1;    // smem reduce stride (odd)
    const int tid = threadIdx.x;
    const int q   = tid / ROWS;
    const int row = tid % ROWS;
    const int gg  = row % 3;
    const int jg  = j0 + row / 3;

    float wreg[QS];
    {
        const float* wrow = wh + (size_t)(gg * K + jg) * K + q * QS;
#pragma unroll
        for (int i = 0; i < QS; i++) wreg[i] = wrow[i];
    }

    __shared__ float4 h4[K * 2];
    __shared__ float  part[8 * PSTR];

    for (int i = tid; i < K * 8; i += NT) { __stcg(&hA[i], 0.f); }
    __syncthreads();

    float bhr = 0.f, bhz = 0.f, bhn = 0.f;
    int fb = 0, fjg = 0, fj = 0;
    if (tid < NP) {
        fb  = tid & 7;
        fj  = tid >> 3;               // 0..OUTS-1
        fjg = j0 + fj;
        bhr = bh[0 * K + fjg];
        bhz = bh[1 * K + fjg];
        bhn = bh[2 * K + fjg];
    }

    // prefetch xg for step 0
    float xgr = 0.f, xgz = 0.f, xgn = 0.f;
    if (tid < NP) {
        const int t0 = reverse_time ? (Sq - 1) : 0;
        const float* xr = xg + ((size_t)fb * Sq + t0) * (3 * K);
        xgr = __ldg(xr + fjg);
        xgz = __ldg(xr + K + fjg);
        xgn = __ldg(xr + 2 * K + fjg);
    }

    float* hsrc = hA;
    float* hdst = hB;
    for (int s = 0; s < Sq; s++) {
        const int t = reverse_time ? (Sq - 1 - s) : s;

        // stage h (L2 -> smem, bypass L1)
        for (int i = tid; i < K * 2; i += NT)
            h4[i] = __ldcg(((const float4*)hsrc) + i);
        __syncthreads();

        float acc[8];
#pragma unroll
        for (int b = 0; b < 8; b++) acc[b] = 0.f;
        const int kb = q * QS;
#pragma unroll
        for (int i = 0; i < QS; i++) {
            const float  w  = wreg[i];
            const float4 lo = h4[(kb + i) * 2];
            const float4 hi = h4[(kb + i) * 2 + 1];
            acc[0] += w * lo.x; acc[1] += w * lo.y;
            acc[2] += w * lo.z; acc[3] += w * lo.w;
            acc[4] += w * hi.x; acc[5] += w * hi.y;
            acc[6] += w * hi.z; acc[7] += w * hi.w;
        }
#pragma unroll
        for (int b = 0; b < 8; b++) part[b * PSTR + q * ROWS + row] = acc[b];
        __syncthreads();

        if (tid < NP) {
            float sr = 0.f, sz = 0.f, sn = 0.f;
#pragma unroll
            for (int qq = 0; qq < Q; qq++) {
                const float* p = &part[fb * PSTR + qq * ROWS + fj * 3];
                sr += p[0]; sz += p[1]; sn += p[2];
            }
            const float hold = ((const float*)h4)[fjg * 8 + fb];

            const float r    = fsig(xgr + sr + bhr);
            const float z    = fsig(xgz + sz + bhz);
            const float nn   = ftanh(xgn + r * (sn + bhn));
            const float hnew = (1.f - z) * nn + z * hold;

            __stcg(&hdst[fjg * 8 + fb], hnew);
            __threadfence();               // release for hdst
            const int to = shift_out ? (t + 1) : t;
            if (to < Sq)
                outbase[((size_t)fb * Sq + to) * H2q + out_off + fjg] = hnew;
            if (s == Sq - 1 && u0base)
                u0base[((size_t)fb * Sq) * H2q + u0_off + fjg] = hnew;

            // prefetch xg for step s+1 (hides LDG off the post-barrier chain)
            if (s + 1 < Sq) {
                const int tn = reverse_time ? (Sq - 2 - s) : (s + 1);
                const float* xr = xg + ((size_t)fb * Sq + tn) * (3 * K);
                xgr = __ldg(xr + fjg);
                xgz = __ldg(xr + K + fjg);
                xgn = __ldg(xr + 2 * K + fjg);
            }
        }
        grid_barrier_c(bar_idx, bar_n);
        float* tmp = hsrc; hsrc = hdst; hdst = tmp;
    }
}

// fwd = CTAs [0,64) (bar 0), bwd = CTAs [64,128) (bar 1); run concurrently.
__global__ void __launch_bounds__(192, 1)
scan_fb(const float* xgf, const float* xgb,
        const float* whf, const float* bhf,
        const float* whb, const float* bhb)
{
    const int  cta = blockIdx.x;
    const bool isb = cta >= 64;
    scan_worker<Hq, 4, 192>((isb ? cta - 64 : cta) * 4,
                    isb ? xgb : xgf,
                    isb ? whb : whf,
                    isb ? bhb : bhf,
                    isb ? g_hb[0] : g_hf[0],
                    isb ? g_hb[1] : g_hf[1],
                    g_bigru, isb ? Hq : 0,
                    isb ? 1 : 0,
                    isb ? 1 : 0, 64,
                    g_U, isb ? 0 : Hq,   // hidden_cat = [hT_b | hT_f]
                    0);
}

// uni: 64 CTAs, 8 outputs each, 384 threads (halves arrivals/pollers/spread).
__global__ void __launch_bounds__(384, 1)
scan_uni(const float* xgu, const float* whu, const float* bhu)
{
    scan_worker<H2q, 8, 384>(blockIdx.x * 8, xgu, whu, bhu,
                     g_hu[0], g_hu[1],
                     g_U, 0,
                     0,
                     2, 64,
                     nullptr, 0,
                     1);                 // U[:, t+1] = uni_out[:, t]
}

// ---------------- GEMM: C = A @ W^T + bias (double-buffered, occ 2) ----------------
__global__ void __launch_bounds__(256, 2)
gemm_abt(const float* __restrict__ A, const float* __restrict__ W,
         const float* __restrict__ bias, float* __restrict__ C,
         int M, int N, int K,
         long long sA, long long sW, long long sC)
{
    A += (size_t)blockIdx.z * sA;
    W += (size_t)blockIdx.z * sW;
    C += (size_t)blockIdx.z * sC;

    __shared__ float As[2][8][132];
    __shared__ float Ws[2][8][132];

    const int tid = threadIdx.x;
    const int tx = tid % 16, ty = tid / 16;
    const int m0 = blockIdx.y * 128, n0 = blockIdx.x * 128;
    const int r = tid >> 1, cq = tid & 1;

    const float* Aptr = A + (size_t)(m0 + r) * K + cq * 4;
    const bool   wok  = (n0 + r) < N;
    const float* Wptr = W + (size_t)(n0 + r) * K + cq * 4;

    float acc[8][8];
#pragma unroll
    for (int i = 0; i < 8; i++)
#pragma unroll
        for (int jj = 0; jj < 8; jj++) acc[i][jj] = 0.f;

    float4 a4 = *(const float4*)(Aptr);
    float4 w4 = wok ? *(const float4*)(Wptr) : make_float4(0.f,0.f,0.f,0.f);
    As[0][cq * 4 + 0][r] = a4.x; As[0][cq * 4 + 1][r] = a4.y;
    As[0][cq * 4 + 2][r] = a4.z; As[0][cq * 4 + 3][r] = a4.w;
    Ws[0][cq * 4 + 0][r] = w4.x; Ws[0][cq * 4 + 1][r] = w4.y;
    Ws[0][cq * 4 + 2][r] = w4.z; Ws[0][cq * 4 + 3][r] = w4.w;
    __syncthreads();

    int p = 0;
    for (int k0 = 0; k0 < K; k0 += 8) {
        const bool more = (k0 + 8 < K);
        if (more) {
            a4 = *(const float4*)(Aptr + k0 + 8);
            w4 = wok ? *(const float4*)(Wptr + k0 + 8) : make_float4(0.f,0.f,0.f,0.f);
        }
#pragma unroll
        for (int k = 0; k < 8; k++) {
            float mreg[8], nreg[8];
            *(float4*)&mreg[0] = *(const float4*)&As[p][k][ty * 8];
            *(float4*)&mreg[4] = *(const float4*)&As[p][k][ty * 8 + 4];
            *(float4*)&nreg[0] = *(const float4*)&Ws[p][k][tx * 8];
            *(float4*)&nreg[4] = *(const float4*)&Ws[p][k][tx * 8 + 4];
#pragma unroll
            for (int i = 0; i < 8; i++)
#pragma unroll
                for (int jj = 0; jj < 8; jj++)
                    acc[i][jj] += mreg[i] * nreg[jj];
        }
        if (more) {
            const int pn = p ^ 1;
            As[pn][cq * 4 + 0][r] = a4.x; As[pn][cq * 4 + 1][r] = a4.y;
            As[pn][cq * 4 + 2][r] = a4.z; As[pn][cq * 4 + 3][r] = a4.w;
            Ws[pn][cq * 4 + 0][r] = w4.x; Ws[pn][cq * 4 + 1][r] = w4.y;
            Ws[pn][cq * 4 + 2][r] = w4.z; Ws[pn][cq * 4 + 3][r] = w4.w;
            __syncthreads();
            p = pn;
        }
    }

    float breg[8];
#pragma unroll
    for (int jj = 0; jj < 8; jj++) {
        const int c = n0 + tx * 8 + jj;
        breg[jj] = (bias && c < N) ? bias[c] : 0.f;
    }
    const int c0 = n0 + tx * 8;
#pragma unroll
    for (int i = 0; i < 8; i++) {
        float* crow = C + (size_t)(m0 + ty * 8 + i) * N;
        if (c0 < N) {
            float4 o = { acc[i][0] + breg[0], acc[i][1] + breg[1],
                         acc[i][2] + breg[2], acc[i][3] + breg[3] };
            *(float4*)(crow + c0) = o;
        }
        if (c0 + 4 < N) {
            float4 o = { acc[i][4] + breg[4], acc[i][5] + breg[5],
                         acc[i][6] + breg[6], acc[i][7] + breg[7] };
            *(float4*)(crow + c0 + 4) = o;
        }
    }
}

// ---------------- GEMM: C = A @ B + bias (double-buffered, occ 2) ----------------
__global__ void __launch_bounds__(256, 2)
gemm_ab(const float* __restrict__ A, const float* __restrict__ B,
        const float* __restrict__ bias, float* __restrict__ C,
        int M, int N, int K,
        long long sA, long long sB, long long sC)
{
    A += (size_t)blockIdx.z * sA;
    B += (size_t)blockIdx.z * sB;
    C += (size_t)blockIdx.z * sC;

    __shared__ float As[2][8][132];
    __shared__ float Bs[2][8][132];

    const int tid = threadIdx.x;
    const int tx = tid % 16, ty = tid / 16;
    const int m0 = blockIdx.y * 128, n0 = blockIdx.x * 128;
    const int r = tid >> 1, cq = tid & 1;
    const int kk = tid >> 5, nq = tid & 31;

    const float* Aptr = A + (size_t)(m0 + r) * K + cq * 4;
    const bool   bok  = (n0 + nq * 4) < N;
    const float* Bptr = B + (size_t)kk * N + n0 + nq * 4;

    float acc[8][8];
#pragma unroll
    for (int i = 0; i < 8; i++)
#pragma unroll
        for (int jj = 0; jj < 8; jj++) acc[i][jj] = 0.f;

    float4 a4 = *(const float4*)(Aptr);
    float4 b4 = bok ? *(const float4*)(Bptr) : make_float4(0.f,0.f,0.f,0.f);
    As[0][cq * 4 + 0][r] = a4.x; As[0][cq * 4 + 1][r] = a4.y;
    As[0][cq * 4 + 2][r] = a4.z; As[0][cq * 4 + 3][r] = a4.w;
    *(float4*)&Bs[0][kk][nq * 4] = b4;
    __syncthreads();

    int p = 0;
    for (int k0 = 0; k0 < K; k0 += 8) {
        const bool more = (k0 + 8 < K);
        if (more) {
            a4 = *(const float4*)(Aptr + k0 + 8);
            b4 = bok ? *(const float4*)(Bptr + (size_t)(k0 + 8) * N)
                     : make_float4(0.f,0.f,0.f,0.f);
        }
#pragma unroll
        for (int k = 0; k < 8; k++) {
            float mreg[8], nreg[8];
            *(float4*)&mreg[0] = *(const float4*)&As[p][k][ty * 8];
            *(float4*)&mreg[4] = *(const float4*)&As[p][k][ty * 8 + 4];
            *(float4*)&nreg[0] = *(const float4*)&Bs[p][k][tx * 8];
            *(float4*)&nreg[4] = *(const float4*)&Bs[p][k][tx * 8 + 4];
#pragma unroll
            for (int i = 0; i < 8; i++)
#pragma unroll
                for (int jj = 0; jj < 8; jj++)
                    acc[i][jj] += mreg[i] * nreg[jj];
        }
        if (more) {
            const int pn = p ^ 1;
            As[pn][cq * 4 + 0][r] = a4.x; As[pn][cq * 4 + 1][r] = a4.y;
            As[pn][cq * 4 + 2][r] = a4.z; As[pn][cq * 4 + 3][r] = a4.w;
            *(float4*)&Bs[pn][kk][nq * 4] = b4;
            __syncthreads();
            p = pn;
        }
    }

    float breg[8];
#pragma unroll
    for (int jj = 0; jj < 8; jj++) {
        const int c = n0 + tx * 8 + jj;
        breg[jj] = (bias && c < N) ? bias[c] : 0.f;
    }
    const int c0 = n0 + tx * 8;
#pragma unroll
    for (int i = 0; i < 8; i++) {
        float* crow = C + (size_t)(m0 + ty * 8 + i) * N;
        if (c0 < N) {
            float4 o = { acc[i][0] + breg[0], acc[i][1] + breg[1],
                         acc[i][2] + breg[2], acc[i][3] + breg[3] };
            *(float4*)(crow + c0) = o;
        }
        if (c0 + 4 < N) {
            float4 o = { acc[i][4] + breg[4], acc[i][5] + breg[5],
                         acc[i][6] + breg[6], acc[i][7] + breg[7] };
            *(float4*)(crow + c0 + 4) = o;
        }
    }
}

// ---------------- row softmax over 1024 cols ----------------
__global__ void __launch_bounds__(256, 1)
softmax_rows(float* __restrict__ E)
{
    float4* e4 = (float4*)(E + (size_t)blockIdx.x * Sq);
    const int tid = threadIdx.x;
    float4 v = e4[tid];

    float m = fmaxf(fmaxf(v.x, v.y), fmaxf(v.z, v.w));
#pragma unroll
    for (int o = 16; o > 0; o >>= 1)
        m = fmaxf(m, __shfl_xor_sync(0xffffffffu, m, o));
    __shared__ float wredm[8];
    if ((tid & 31) == 0) wredm[tid >> 5] = m;
    __syncthreads();
    float mm = wredm[0];
#pragma unroll
    for (int i = 1; i < 8; i++) mm = fmaxf(mm, wredm[i]);

    v.x = __expf(v.x - mm); v.y = __expf(v.y - mm);
    v.z = __expf(v.z - mm); v.w = __expf(v.w - mm);
    float s = v.x + v.y + v.z + v.w;
#pragma unroll
    for (int o = 16; o > 0; o >>= 1)
        s += __shfl_xor_sync(0xffffffffu, s, o);
    __shared__ float wreds[8];
    if ((tid & 31) == 0) wreds[tid >> 5] = s;
    __syncthreads();
    float ss = 0.f;
#pragma unroll
    for (int i = 0; i < 8; i++) ss += wreds[i];

    const float inv = __fdividef(1.f, ss);
    v.x *= inv; v.y *= inv; v.z *= inv; v.w *= inv;
    e4[tid] = v;
}

__global__ void embed_k(const int* __restrict__ tok, const float* __restrict__ emb)
{
    const int i = blockIdx.x * blockDim.x + threadIdx.x;
    const int n4 = Bq * Sq * Eq / 4;
    if (i < n4) {
        const int row = i / (Eq / 4);
        const int c   = i % (Eq / 4);
        const int t   = tok[row];
        ((float4*)g_x)[i] = ((const float4*)(emb + (size_t)t * Eq))[c];
    }
}

__global__ void ft_k()
{
    const int i = blockIdx.x * blockDim.x + threadIdx.x;
    const int n4 = Bq * Sq * H2q / 4;
    if (i < n4) {
        const float4 a = ((const float4*)g_cfc)[i];
        const float4 b = ((const float4*)g_cfcfc)[i];
        const float4 c = ((const float4*)g_htfc)[i];
        const float4 d = ((const float4*)g_bigru)[i];
        float4 o;
        o.x = a.x * fsig(b.x + c.x) + d.x;
        o.y = a.y * fsig(b.y + c.y) + d.y;
        o.z = a.z * fsig(b.z + c.z) + d.z;
        o.w = a.w * fsig(b.w + c.w) + d.w;
        ((float4*)g_ft)[i] = o;
    }
}

// ---------------- launch ----------------
static float* sym(const void* s) {
    void* p = nullptr;
    cudaGetSymbolAddress(&p, s);
    return (float*)p;
}

extern "C" void kernel_launch(void* const* d_in, const int* in_sizes, int n_in,
                              void* d_out, int out_size)
{
    (void)in_sizes; (void)n_in; (void)out_size;
    const int*   tok     = (const int*)  d_in[0];
    const float* emb     = (const float*)d_in[2];
    const float* wi_f    = (const float*)d_in[3];
    const float* wh_f    = (const float*)d_in[4];
    const float* bi_f    = (const float*)d_in[5];
    const float* bh_f    = (const float*)d_in[6];
    const float* wi_b    = (const float*)d_in[7];
    const float* wh_b    = (const float*)d_in[8];
    const float* bi_b    = (const float*)d_in[9];
    const float* bh_b    = (const float*)d_in[10];
    const float* uwi     = (const float*)d_in[11];
    const float* uwh     = (const float*)d_in[12];
    const float* ubi     = (const float*)d_in[13];
    const float* ubh     = (const float*)d_in[14];
    const float* w_attn  = (const float*)d_in[15];
    const float* b_attn  = (const float*)d_in[16];
    const float* w_afc   = (const float*)d_in[17];
    const float* b_afc   = (const float*)d_in[18];
    const float* w_ht    = (const float*)d_in[19];
    const float* b_ht    = (const float*)d_in[20];
    const float* w_out   = (const float*)d_in[21];
    const float* b_out   = (const float*)d_in[22];
    float* out = (float*)d_out;

    float* x     = sym(g_x);
    float* xgf   = sym(g_xgf);
    float* xgb   = sym(g_xgb);
    float* bigru = sym(g_bigru);
    float* xgu   = sym(g_xgu);
    float* U     = sym(g_U);
    float* energ = sym(g_energ);
    float* ctx   = sym(g_ctx);
    float* cfc   = sym(g_cfc);
    float* cfcfc = sym(g_cfcfc);
    float* htfc  = sym(g_htfc);
    float* ft    = sym(g_ft);

    const long long sU = (long long)Sq * H2q;
    const long long sE = (long long)Sq * Sq;
    const int M = Bq * Sq;                      // 8192

    zero_bar_k<<<1, 32>>>();
    embed_k<<<(Bq*Sq*Eq/4 + 255)/256, 256>>>(tok, emb);

    gemm_abt<<<dim3(6, 64, 1), 256>>>(x, wi_f, bi_f, xgf, M, 3*Hq, Eq, 0, 0, 0);
    gemm_abt<<<dim3(6, 64, 1), 256>>>(x, wi_b, bi_b, xgb, M, 3*Hq, Eq, 0, 0, 0);

    scan_fb<<<128, 192>>>(xgf, xgb, wh_f, bh_f, wh_b, bh_b);

    gemm_abt<<<dim3(12, 64, 1), 256>>>(bigru, uwi, ubi, xgu, M, 3*H2q, H2q, 0, 0, 0);

    scan_uni<<<64, 384>>>(xgu, uwh, ubh);

    gemm_abt<<<dim3(8, 8, Bq), 256>>>(U, bigru, nullptr, energ,
                                      Sq, Sq, H2q, sU, sU, sE);
    softmax_rows<<<M, 256>>>(energ);
    gemm_ab<<<dim3(4, 8, Bq), 256>>>(energ, bigru, nullptr, ctx,
                                     Sq, H2q, Sq, sE, sU, sU);

    gemm_abt<<<dim3(4, 64, 1), 256>>>(ctx,   w_attn, b_attn, cfc,   M, H2q, H2q, 0, 0, 0);
    gemm_abt<<<dim3(4, 64, 1), 256>>>(cfc,   w_afc,  b_afc,  cfcfc, M, H2q, H2q, 0, 0, 0);
    gemm_abt<<<dim3(4, 64, 1), 256>>>(bigru, w_ht,   b_ht,   htfc,  M, H2q, H2q, 0, 0, 0);

    ft_k<<<(Bq*Sq*H2q/4 + 255)/256, 256>>>();

    gemm_abt<<<dim3(1, 64, 1), 256>>>(ft, w_out, b_out, out, M, Cq, H2q, 0, 0, 0);
}